// round 15
// baseline (speedup 1.0000x reference)
#include <cuda_runtime.h>
#include <cuda_bf16.h>

// out[b, j, k] = sum_d x[b, j+1, d] * W[j, d, k] + bias[j, k]
// B = 65536, NODES = 13, D = 256, J = 12, K = 2
//
// Persistent-j warps, SOFTWARE-PIPELINED (ping-pong double buffer):
//   - grid = 3 CTAs/SM x 128 threads -> total warps = num_sms*12, single
//     wave guaranteed; warp w owns joint j = w % 12 forever, so W[j] and
//     bias[j] live in registers for the whole kernel.
//   - loop: issue next group's 8 streaming LDG.128 into buffer B, THEN
//     compute/reduce/store buffer A. Steady state always has a full load
//     batch in flight -> DRAM latency never exposed (this is what R5 got
//     wrong), and there are no wave transitions (what R9 pays ~30x).
//   - merged butterfly reduction: 16 SHFL for 8 sums, one predicated
//     scattered STG.32 from 8 lanes.

#define NODES 13
#define DIM   256
#define NJ    12
#define RB    4

__device__ __forceinline__ void load_group(const float* __restrict__ x,
                                           int b0, int node, int lane,
                                           float4 x0[RB], float4 x1[RB])
{
#pragma unroll
    for (int r = 0; r < RB; r++) {
        const float4* __restrict__ xr = reinterpret_cast<const float4*>(
            x + ((long long)(b0 + r) * NODES + node) * DIM);
        x0[r] = __ldcs(xr + lane);
        x1[r] = __ldcs(xr + lane + 32);
    }
}

__device__ __forceinline__ void compute_store(const float4 x0[RB], const float4 x1[RB],
                                              float4 wa0, float4 wa1,
                                              float4 wb0, float4 wb1,
                                              int b0, int j, float b_out,
                                              int k_out, int r_out, bool writer,
                                              int lane, float* __restrict__ out)
{
    float a[2 * RB];
#pragma unroll
    for (int r = 0; r < RB; r++) {
        a[2 * r]     = x0[r].x * wa0.x + x0[r].y * wa0.z
                     + x0[r].z * wa1.x + x0[r].w * wa1.z
                     + x1[r].x * wb0.x + x1[r].y * wb0.z
                     + x1[r].z * wb1.x + x1[r].w * wb1.z;
        a[2 * r + 1] = x0[r].x * wa0.y + x0[r].y * wa0.w
                     + x0[r].z * wa1.y + x0[r].w * wa1.w
                     + x1[r].x * wb0.y + x1[r].y * wb0.w
                     + x1[r].z * wb1.y + x1[r].w * wb1.w;
    }

    // merged butterfly: 16 SHFL total, fold value set in half each level
#pragma unroll
    for (int v = 0; v < 8; v++)
        a[v] += __shfl_xor_sync(0xFFFFFFFFu, a[v], 16);
    float m[4];
#pragma unroll
    for (int i = 0; i < 4; i++)
        m[i] = (lane & 16) ? a[2 * i + 1] : a[2 * i];
#pragma unroll
    for (int i = 0; i < 4; i++)
        m[i] += __shfl_xor_sync(0xFFFFFFFFu, m[i], 8);
    float n0 = (lane & 8) ? m[1] : m[0];
    float n1 = (lane & 8) ? m[3] : m[2];
    n0 += __shfl_xor_sync(0xFFFFFFFFu, n0, 4);
    n1 += __shfl_xor_sync(0xFFFFFFFFu, n1, 4);
    float p = (lane & 4) ? n1 : n0;
    p += __shfl_xor_sync(0xFFFFFFFFu, p, 2);
    p += __shfl_xor_sync(0xFFFFFFFFu, p, 1);
    // lane l holds sum for k = (l>>4)&1, r = ((l>>3)&1) + 2*((l>>2)&1)

    if (writer)
        out[((b0 + r_out) * NJ + j) * 2 + k_out] = p + b_out;
}

__global__ void __launch_bounds__(128)
detok_kernel(const float* __restrict__ x,
             const float* __restrict__ W,
             const float* __restrict__ bias,
             float* __restrict__ out,
             int B)
{
    int wid  = (blockIdx.x * blockDim.x + threadIdx.x) >> 5;
    int lane = threadIdx.x & 31;
    int total_warps = (gridDim.x * blockDim.x) >> 5;   // multiple of 12

    int j  = wid % NJ;
    int g0 = wid / NJ;
    int gs = total_warps / NJ;
    int node = j + 1;
    int ngroups = B / RB;

    // ---- W[j] resident in registers for the whole kernel ----
    const float4* __restrict__ wr =
        reinterpret_cast<const float4*>(W + j * (DIM * 2));
    float4 wa0 = wr[2 * lane];
    float4 wa1 = wr[2 * lane + 1];
    float4 wb0 = wr[64 + 2 * lane];
    float4 wb1 = wr[64 + 2 * lane + 1];

    float2 bj = reinterpret_cast<const float2*>(bias)[j];
    int k_out = (lane >> 4) & 1;
    int r_out = ((lane >> 3) & 1) + 2 * ((lane >> 2) & 1);
    float b_out = k_out ? bj.y : bj.x;
    bool writer = (lane & 3) == 0;

    // ---- ping-pong pipelined main loop ----
    float4 A0[RB], A1[RB], B0[RB], B1[RB];

    int gA = g0;
    if (gA < ngroups)
        load_group(x, gA * RB, node, lane, A0, A1);

    while (gA < ngroups) {
        int gB  = gA + gs;
        int gA2 = gA + 2 * gs;

        if (gB < ngroups)
            load_group(x, gB * RB, node, lane, B0, B1);        // prefetch B
        compute_store(A0, A1, wa0, wa1, wb0, wb1,
                      gA * RB, j, b_out, k_out, r_out, writer, lane, out);

        if (gA2 < ngroups)
            load_group(x, gA2 * RB, node, lane, A0, A1);       // prefetch A'
        if (gB < ngroups)
            compute_store(B0, B1, wa0, wa1, wb0, wb1,
                          gB * RB, j, b_out, k_out, r_out, writer, lane, out);

        gA = gA2;
    }
}

extern "C" void kernel_launch(void* const* d_in, const int* in_sizes, int n_in,
                              void* d_out, int out_size)
{
    const float* x    = (const float*)d_in[0];   // (B, 13, 256)
    const float* W    = (const float*)d_in[1];   // (12, 256, 2)
    const float* bias = (const float*)d_in[2];   // (12, 2)
    float* out = (float*)d_out;                  // (B, 12, 2)

    int B = in_sizes[0] / (NODES * DIM);

    int dev = 0, num_sms = 148;
    cudaGetDevice(&dev);
    cudaDeviceGetAttribute(&num_sms, cudaDevAttrMultiProcessorCount, dev);

    // 3 CTAs per SM x 4 warps = 12 warps/SM; total warps = num_sms*12,
    // divisible by NJ=12 and guaranteed single-wave at <=170 regs.
    int blocks = num_sms * 3;
    detok_kernel<<<blocks, 128>>>(x, W, bias, out, B);
}